// round 16
// baseline (speedup 1.0000x reference)
#include <cuda_runtime.h>
#include <cuda_bf16.h>
#include <math.h>

#define NPTS 4096
#define BATCH 8
#define NROWS (BATCH*NPTS)     // 32768
#define DK 100
#define KNB 20
#define TPB1 256
#define CANDMAX 224
#define BLKX 111               // blocks per batch; 8*111=888 = 2 exact waves of 444

// ---------------- device scratch (no runtime allocation allowed) ----------------
__device__ double g_msum[64];
__device__ double g_msumsq[64];
__device__ double g_M1[6];
__device__ double g_M2[21];
__device__ double g_hsum[512];          // [b][o]
__device__ float  g_mpreT[64 * NROWS];  // TRANSPOSED: [o][row] (coalesced k3 reads)
__device__ int    g_idx[NROWS * DK];    // [row][100]
__device__ int    g_selidx[NROWS * KNB];// [row][20]
__device__ float  g_rm[64], g_meanm[64];   // m-BN rsqrt / mean
__device__ float  g_r1[64], g_mean1[64];   // h-BN rsqrt / mean
__device__ float  g_s2[512];            // SE gate [b][o]
__device__ float  g_Wt[DK * 64];        // W_op1 transposed: g_Wt[j*64+o] = W_op1[o*DK+j]

// ---------------- f32x2 packed helpers (per-lane IEEE identical to scalar) ----------------
__device__ __forceinline__ unsigned long long pk2(float lo, float hi) {
    unsigned long long r; asm("mov.b64 %0, {%1, %2};" : "=l"(r) : "f"(lo), "f"(hi)); return r;
}
__device__ __forceinline__ void upk2(float& lo, float& hi, unsigned long long v) {
    asm("mov.b64 {%0, %1}, %2;" : "=f"(lo), "=f"(hi) : "l"(v));
}
__device__ __forceinline__ unsigned long long f2mul(unsigned long long a, unsigned long long b) {
    unsigned long long r; asm("mul.rn.f32x2 %0, %1, %2;" : "=l"(r) : "l"(a), "l"(b)); return r;
}
__device__ __forceinline__ unsigned long long f2fma(unsigned long long a, unsigned long long b, unsigned long long c) {
    unsigned long long r; asm("fma.rn.f32x2 %0, %1, %2, %3;" : "=l"(r) : "l"(a), "l"(b), "l"(c)); return r;
}
__device__ __forceinline__ unsigned long long f2add(unsigned long long a, unsigned long long b) {
    unsigned long long r; asm("add.rn.f32x2 %0, %1, %2;" : "=l"(r) : "l"(a), "l"(b)); return r;
}

// ---------------- K0: zero accumulators + transpose W_op1 ----------------
__global__ void k0_zero(const float* __restrict__ W_op1) {
    int t = threadIdx.x;
    if (t < 64) { g_msum[t] = 0.0; g_msumsq[t] = 0.0; }
    if (t < 6)  g_M1[t] = 0.0;
    if (t < 21) g_M2[t] = 0.0;
    if (t < 512) g_hsum[t] = 0.0;
    for (int i = t; i < DK * 64; i += 512) {
        int j = i >> 6, o = i & 63;
        g_Wt[i] = W_op1[o * DK + j];
    }
}

// no-op spacer so k1 lands on the ncu-captured launch index
__global__ void k_dummy() {}

// ---------------- packed-16-bit histogram rank search (256 threads, unpadded) ----------------
template <int WPT>
__device__ __forceinline__ int scan_find_packed(const unsigned* h32, int rankv,
                                                int tid, int lane, int wid,
                                                unsigned* warpS, int* bc) {
    unsigned words[WPT];
    int wbase = tid * WPT;
    unsigned local = 0;
    #pragma unroll
    for (int i = 0; i < WPT; ++i) {
        unsigned w = h32[wbase + i];
        words[i] = w;
        local += (w & 0xFFFFu) + (w >> 16);
    }
    unsigned v = local;
    #pragma unroll
    for (int off = 1; off < 32; off <<= 1) {
        unsigned t2 = __shfl_up_sync(0xFFFFFFFFu, v, off);
        if (lane >= off) v += t2;
    }
    if (lane == 31) warpS[wid] = v;
    __syncthreads();
    if (tid == 0) {
        unsigned s = 0;
        #pragma unroll
        for (int w = 0; w < 8; ++w) { unsigned t2 = warpS[w]; warpS[w] = s; s += t2; }
    }
    __syncthreads();
    unsigned incl = v + warpS[wid];
    unsigned excl = incl - local;
    if (excl < (unsigned)rankv && (unsigned)rankv <= incl) {
        unsigned c = excl;
        #pragma unroll
        for (int i = 0; i < WPT; ++i) {
            unsigned lo = words[i] & 0xFFFFu;
            if (c < (unsigned)rankv && (unsigned)rankv <= c + lo) { bc[0] = (wbase + i) * 2;     bc[1] = (int)c; break; }
            c += lo;
            unsigned hi = words[i] >> 16;
            if (c < (unsigned)rankv && (unsigned)rankv <= c + hi) { bc[0] = (wbase + i) * 2 + 1; bc[1] = (int)c; break; }
            c += hi;
        }
    }
    __syncthreads();
    return bc[0];
}

// scalar packed histogram increment — proven fastest
__device__ __forceinline__ void hist_add(unsigned* h32, unsigned bin) {
    atomicAdd(&h32[bin >> 1], (bin & 1u) ? 0x10000u : 1u);
}

// ---------------- K1: per-row top-100 select (adaptive threshold + hist fallback) + matmul ----------------
__global__ __launch_bounds__(TPB1, 3) void k1_topk(const float* __restrict__ x) {
    extern __shared__ char smem_raw[];
    float4*   xsp  = (float4*)smem_raw;                                 // [0, 65536): (x0,x1,x2,-xx)
    unsigned* h32  = (unsigned*)(smem_raw + 65536);                     // [65536, 73728) 4096 bins x u16
    unsigned long long* cand = (unsigned long long*)(smem_raw + 73728); // 224*8 = 1792 -> 75520
    float*    metric_s = (float*)(smem_raw + 75520);                    // 512 -> 76032
    unsigned* warpS  = (unsigned*)(smem_raw + 76032);                   // 32
    int*      bc     = (int*)(smem_raw + 76064);                        // 8
    int*      cnt    = (int*)(smem_raw + 76072);                        // 16 (2 ping-pong pairs: fast A, hist B)
    float*    t100_s = (float*)(smem_raw + 76088);                      // 4
    // total 76096  (3 blocks/SM: 3*(76096+1024) = 231.4 KB <= budget)

    int tid = threadIdx.x, lane = tid & 31, wid = tid >> 5;
    int b = blockIdx.y;
    const float* xb = x + b * 3 * NPTS;
    for (int j = tid; j < NPTS; j += TPB1) {
        float a0 = xb[j], a1 = xb[NPTS + j], a2 = xb[2 * NPTS + j];
        // xx with separate roundings (match XLA), then exact negation
        float v = __fadd_rn(__fadd_rn(__fmul_rn(a0, a0), __fmul_rn(a1, a1)), __fmul_rn(a2, a2));
        xsp[j] = make_float4(a0, a1, a2, -v);
    }
    // startup zero of hist + all 4 counters
    for (int i = tid; i < 2048; i += TPB1) h32[i] = 0;
    if (tid < 4) cnt[tid] = 0;
    __syncthreads();

    double msum = 0.0, msq = 0.0;
    int o_out = tid >> 2, quad = tid & 3;
    bool have_t = false;

    // balanced variable row range: 888 blocks -> exactly 2 waves of 444
    int rbeg = (blockIdx.x * NPTS) / BLKX;
    int rend = ((blockIdx.x + 1) * NPTS) / BLKX;

    for (int r = rbeg; r < rend; ++r) {
        int n = r;
        int par = r & 1;
        float4 P = xsp[n];
        float x0n = P.x, x1n = P.y, x2n = P.z, negxxn = P.w;

        // ---- keys via f32x2; pair (j, j+2048): conflict-free LDS.128 ----
        unsigned long long X0 = pk2(x0n, x0n), X1 = pk2(x1n, x1n), X2 = pk2(x2n, x2n);
        unsigned long long TWO = pk2(2.0f, 2.0f), NXN = pk2(negxxn, negxxn);
        unsigned kreg[16];
        #pragma unroll
        for (int p8 = 0; p8 < 8; ++p8) {
            int jA = p8 * 256 + tid;
            float4 A = xsp[jA];
            float4 B = xsp[jA + 2048];
            unsigned long long acc = f2mul(X0, pk2(A.x, B.x));
            acc = f2fma(X1, pk2(A.y, B.y), acc);
            acc = f2fma(X2, pk2(A.z, B.z), acc);
            acc = f2mul(TWO, acc);              // 2*inner (exact doubling)
            acc = f2add(acc, NXN);              // - xx_n
            acc = f2add(acc, pk2(A.w, B.w));    // - xx_j
            float p0, p1; upk2(p0, p1, acc);
            unsigned b0 = __float_as_uint(p0);
            unsigned u0 = (b0 & 0x80000000u) ? ~b0 : (b0 | 0x80000000u);
            kreg[2 * p8] = ~u0;
            unsigned b1v = __float_as_uint(p1);
            unsigned u1 = (b1v & 0x80000000u) ? ~b1v : (b1v | 0x80000000u);
            kreg[2 * p8 + 1] = ~u1;
        }

        int nv = -1;
        bool used_hist = false;

        // ---- FAST PATH: reuse previous row's exact 100th value, scaled ----
        // Superset correctness: if count(keys <= Tu) >= DK then the true top-DK
        // all satisfy key <= Tu; exact rank-by-count below reproduces jax order.
        if (have_t) {
            float t_try = __fmul_rn(t100_s[0], 1.32f);   // p <= 0: more negative = larger superset
            unsigned tb = __float_as_uint(t_try);
            unsigned tu = (tb & 0x80000000u) ? ~tb : (tb | 0x80000000u);
            unsigned Tu = ~tu;
            #pragma unroll
            for (int it = 0; it < 16; ++it) {
                bool pr = kreg[it] <= Tu;
                unsigned m = __ballot_sync(0xFFFFFFFFu, pr);
                if (m) {
                    int leader = __ffs(m) - 1;
                    int base = 0;
                    if (lane == leader) base = atomicAdd(&cnt[par], __popc(m));
                    base = __shfl_sync(0xFFFFFFFFu, base, leader);
                    if (pr) {
                        int pos = base + __popc(m & ((1u << lane) - 1u));
                        int j = ((it >> 1) * 256) + tid + ((it & 1) << 11);
                        if (pos < CANDMAX)
                            cand[pos] = (((unsigned long long)kreg[it]) << 32) | (unsigned)j;
                    }
                }
            }
            __syncthreads();
            int ccnt = cnt[par];
            if (ccnt >= DK && ccnt <= CANDMAX) nv = ccnt;
        }

        // ---- FALLBACK: exact histogram select ----
        if (nv < 0) {
            used_hist = true;
            int rank = DK;
            // level 1: bits [31:20], 4096 bins (pre-zeroed)
            #pragma unroll
            for (int it = 0; it < 16; ++it) hist_add(h32, kreg[it] >> 20);
            __syncthreads();
            int b1 = scan_find_packed<8>(h32, rank, tid, lane, wid, warpS, bc);
            int below = bc[1];
            rank -= below;
            unsigned wv = h32[b1 >> 1];
            unsigned cbin = (b1 & 1) ? (wv >> 16) : (wv & 0xFFFFu);
            unsigned cmpShift = 20, cmpVal = (unsigned)b1;

            if ((unsigned)below + cbin > (unsigned)CANDMAX) {
                // level 2: bits [19:9], 2048 bins
                __syncthreads();    // c-bin reads done before re-zero
                for (int i = tid; i < 1024; i += TPB1) h32[i] = 0;
                __syncthreads();
                #pragma unroll
                for (int it = 0; it < 16; ++it) {
                    unsigned k = kreg[it];
                    if ((int)(k >> 20) == b1) hist_add(h32, (k >> 9) & 0x7FFu);
                }
                __syncthreads();
                int b2 = scan_find_packed<4>(h32, rank, tid, lane, wid, warpS, bc);
                below += bc[1];
                rank -= bc[1];
                unsigned pref23 = ((unsigned)b1 << 11) | (unsigned)b2;
                wv = h32[b2 >> 1];
                cbin = (b2 & 1) ? (wv >> 16) : (wv & 0xFFFFu);
                cmpShift = 9; cmpVal = pref23;
                if ((unsigned)below + cbin > (unsigned)CANDMAX) {
                    // level 3: bits [8:0], 512 bins
                    __syncthreads();
                    for (int i = tid; i < 256; i += TPB1) h32[i] = 0;
                    __syncthreads();
                    #pragma unroll
                    for (int it = 0; it < 16; ++it) {
                        unsigned k = kreg[it];
                        if ((k >> 9) == pref23) hist_add(h32, k & 0x1FFu);
                    }
                    __syncthreads();
                    int b3 = scan_find_packed<1>(h32, rank, tid, lane, wid, warpS, bc);
                    cmpShift = 0; cmpVal = (pref23 << 9) | (unsigned)b3;
                }
            }

            // compaction into slot B
            #pragma unroll
            for (int it = 0; it < 16; ++it) {
                bool pr = (kreg[it] >> cmpShift) <= cmpVal;
                unsigned m = __ballot_sync(0xFFFFFFFFu, pr);
                if (m) {
                    int leader = __ffs(m) - 1;
                    int base = 0;
                    if (lane == leader) base = atomicAdd(&cnt[2 + par], __popc(m));
                    base = __shfl_sync(0xFFFFFFFFu, base, leader);
                    if (pr) {
                        int pos = base + __popc(m & ((1u << lane) - 1u));
                        int j = ((it >> 1) * 256) + tid + ((it & 1) << 11);
                        if (pos < CANDMAX)
                            cand[pos] = (((unsigned long long)kreg[it]) << 32) | (unsigned)j;
                    }
                }
            }
            __syncthreads();
            nv = cnt[2 + par]; if (nv > CANDMAX) nv = CANDMAX;
        }

        // ---- rank-by-counting + conditional hist zero + counter reset ----
        int row = (b << 12) + n;
        if (tid < nv) {
            unsigned long long c = cand[tid];
            int rk = 0;
            int nve = nv & ~1;
            #pragma unroll 4
            for (int i = 0; i < nve; i += 2) {
                ulonglong2 v2 = *reinterpret_cast<const ulonglong2*>(&cand[i]);
                rk += (v2.x < c) ? 1 : 0;
                rk += (v2.y < c) ? 1 : 0;
            }
            if (nv & 1) rk += (cand[nv - 1] < c) ? 1 : 0;
            if (rk < DK) {
                unsigned k = (unsigned)(c >> 32);
                unsigned u = ~k;
                unsigned pb = (u & 0x80000000u) ? (u ^ 0x80000000u) : ~u;
                metric_s[rk] = -__uint_as_float(pb);
                g_idx[row * DK + rk] = (int)(unsigned)(c & 0xFFFFFFFFull);
                if (rk == DK - 1) t100_s[0] = __uint_as_float(pb);  // exact 100th p for next row
            }
        }
        if (used_hist && tid >= 128) {
            int z = tid - 128;
            uint4* h4 = (uint4*)h32;         // 2048 words = 512 uint4
            uint4 zz = make_uint4(0, 0, 0, 0);
            #pragma unroll
            for (int i = 0; i < 4; ++i)
                h4[i * 128 + z] = zz;        // lane stride 16B: conflict-free STS.128
        }
        if (tid == 0) { cnt[par ^ 1] = 0; cnt[2 + (par ^ 1)] = 0; }
        __syncthreads();
        have_t = true;

        // ---- matmul m_pre = W . metric : 4 threads per output, transposed W reads ----
        // (no trailing sync: overlaps next row's key compute)
        {
            const float* wcol = g_Wt + (quad * 25) * 64 + o_out;
            const float* ms = metric_s + quad * 25;
            float acc = 0.0f;
            #pragma unroll
            for (int j2 = 0; j2 < 25; ++j2) acc = fmaf(wcol[j2 * 64], ms[j2], acc);
            acc += __shfl_xor_sync(0xFFFFFFFFu, acc, 1);
            acc += __shfl_xor_sync(0xFFFFFFFFu, acc, 2);
            if (quad == 0) {
                g_mpreT[o_out * NROWS + row] = acc;   // transposed store (coalesced k3 reads)
                msum += (double)acc;
                msq  += (double)acc * (double)acc;
            }
        }
    }
    if (quad == 0) {
        atomicAdd(&g_msum[o_out], msum);
        atomicAdd(&g_msumsq[o_out], msq);
    }
}

// ---------------- K2: BN params for m ----------------
__global__ void k2_mbn() {
    int o = threadIdx.x;
    if (o < 64) {
        double S = (double)NROWS;
        double mean = g_msum[o] / S;
        double var = g_msumsq[o] / S - mean * mean;
        g_rm[o] = rsqrtf((float)var + 1e-5f);
        g_meanm[o] = (float)mean;
    }
}

// ---------------- K3: value bins + dilated select + feat moments (thread per point) ----------------
__global__ __launch_bounds__(256) void k3_value(const float* __restrict__ x,
                                                const float* __restrict__ W_op11,
                                                const float* __restrict__ b_op11,
                                                const float* __restrict__ g_op1,
                                                const float* __restrict__ b_op1) {
    __shared__ float s_mean[64], s_r[64], s_gm[64], s_bt[64], s_w[64];
    int tid = threadIdx.x;
    int lane = tid & 31;
    if (tid < 64) {
        s_mean[tid] = g_meanm[tid]; s_r[tid] = g_rm[tid];
        s_gm[tid] = g_op1[tid];     s_bt[tid] = b_op1[tid];
        s_w[tid] = W_op11[tid];
    }
    __syncthreads();
    int p = blockIdx.x * 256 + tid;     // grid is exactly NROWS/256 blocks
    int b = p >> 12, n = p & 4095;
    const float* mp = g_mpreT + p;      // transposed: mp[o*NROWS] coalesced across lanes
    float t = 0.0f;
    #pragma unroll 8
    for (int o = 0; o < 64; ++o) {
        float v = mp[o * NROWS];
        float xn = __fmul_rn(__fsub_rn(v, s_mean[o]), s_r[o]);
        float vv = __fadd_rn(__fmul_rn(xn, s_gm[o]), s_bt[o]);
        vv = vv >= 0.0f ? vv : __fmul_rn(0.2f, vv);
        t = fmaf(s_w[o], vv, t);
    }
    t = __fadd_rn(t, b_op11[0]);
    float mm = __fadd_rn(__fmul_rn(5.0f, 1.0f / (1.0f + expf(t))), 0.5f);
    int val = 0;
    if      (mm >= 0.5f && mm < 1.5f) val = 1;
    else if (mm >= 1.5f && mm < 2.5f) val = 2;
    else if (mm >= 2.5f && mm < 3.5f) val = 3;
    else if (mm >= 3.5f && mm < 4.5f) val = 4;
    else if (mm >= 4.5f && mm <= 5.5f) val = 5;

    const float* xb = x + b * 3 * NPTS;
    float c0 = xb[n], c1 = xb[NPTS + n], c2 = xb[2 * NPTS + n];
    const int* ip = g_idx + p * DK;
    int* sp = g_selidx + p * KNB;
    float M1l[6] = {0, 0, 0, 0, 0, 0};
    float M2l[21];
    #pragma unroll
    for (int i = 0; i < 21; ++i) M2l[i] = 0.0f;
    #pragma unroll 4
    for (int k = 0; k < KNB; ++k) {
        int id = ip[k * val];
        sp[k] = id;
        float n0 = xb[id], n1 = xb[NPTS + id], n2 = xb[2 * NPTS + id];
        float f[6] = {n0 - c0, n1 - c1, n2 - c2, c0, c1, c2};
        #pragma unroll
        for (int i = 0; i < 6; ++i) M1l[i] += f[i];
        #pragma unroll
        for (int i = 0; i < 6; ++i)
            #pragma unroll
            for (int j = 0; j <= i; ++j)
                M2l[i * (i + 1) / 2 + j] += f[i] * f[j];
    }
    #pragma unroll
    for (int i = 0; i < 6; ++i) {
        float v = M1l[i];
        #pragma unroll
        for (int off = 16; off > 0; off >>= 1) v += __shfl_xor_sync(0xFFFFFFFFu, v, off);
        if (lane == 0) atomicAdd(&g_M1[i], (double)v);
    }
    #pragma unroll
    for (int i = 0; i < 21; ++i) {
        float v = M2l[i];
        #pragma unroll
        for (int off = 16; off > 0; off >>= 1) v += __shfl_xor_sync(0xFFFFFFFFu, v, off);
        if (lane == 0) atomicAdd(&g_M2[i], (double)v);
    }
}

// ---------------- K3.5: BN params for h (moment trick) ----------------
__global__ void k35_hbn(const float* __restrict__ W1) {
    int o = threadIdx.x;
    if (o < 64) {
        double S = (double)NROWS * KNB;
        double w[6];
        #pragma unroll
        for (int c = 0; c < 6; ++c) w[c] = (double)W1[o * 6 + c];
        double mean = 0.0;
        #pragma unroll
        for (int c = 0; c < 6; ++c) mean += w[c] * g_M1[c];
        mean /= S;
        double ex2 = 0.0;
        #pragma unroll
        for (int i = 0; i < 6; ++i)
            #pragma unroll
            for (int j = 0; j <= i; ++j)
                ex2 += (i == j ? 1.0 : 2.0) * w[i] * w[j] * g_M2[i * (i + 1) / 2 + j];
        ex2 /= S;
        double var = ex2 - mean * mean;
        g_r1[o] = rsqrtf((float)var + 1e-5f);
        g_mean1[o] = (float)mean;
    }
}

// ---------------- K4: edge conv, BN+lrelu+max over k, write h, SE sums ----------------
__global__ __launch_bounds__(256) void k4_h(const float* __restrict__ x,
                                            const float* __restrict__ W1,
                                            const float* __restrict__ g1,
                                            const float* __restrict__ b1,
                                            float* __restrict__ out) {
    __shared__ float feat_s[KNB][6][32];
    __shared__ float h_s[64][33];
    __shared__ float W1s[64 * 6];
    __shared__ float r1s[64], mean1s[64], g1s[64], b1s[64];
    int tid = threadIdx.x;
    int lane = tid & 31;
    int p0 = blockIdx.x * 32;
    int b = p0 >> 12;
    int nbase = p0 & 4095;
    for (int i = tid; i < 384; i += 256) W1s[i] = W1[i];
    if (tid < 64) {
        r1s[tid] = g_r1[tid]; mean1s[tid] = g_mean1[tid];
        g1s[tid] = g1[tid];   b1s[tid] = b1[tid];
    }
    __syncthreads();
    const float* xb = x + b * 3 * NPTS;
    for (int t = tid; t < 32 * KNB; t += 256) {
        int pt = t / KNB, k = t % KNB;
        int p = p0 + pt, n = nbase + pt;
        int id = g_selidx[p * KNB + k];
        float c0 = xb[n], c1 = xb[NPTS + n], c2 = xb[2 * NPTS + n];
        float n0 = xb[id], n1 = xb[NPTS + id], n2 = xb[2 * NPTS + id];
        feat_s[k][0][pt] = n0 - c0;
        feat_s[k][1][pt] = n1 - c1;
        feat_s[k][2][pt] = n2 - c2;
        feat_s[k][3][pt] = c0;
        feat_s[k][4][pt] = c1;
        feat_s[k][5][pt] = c2;
    }
    __syncthreads();
    for (int e = tid; e < 2048; e += 256) {
        int o = e >> 5, pt = e & 31;
        float r = r1s[o], mn = mean1s[o], gg = g1s[o], bb = b1s[o];
        float w0 = W1s[o * 6 + 0], w1 = W1s[o * 6 + 1], w2 = W1s[o * 6 + 2];
        float w3 = W1s[o * 6 + 3], w4 = W1s[o * 6 + 4], w5 = W1s[o * 6 + 5];
        float best = -1e30f;
        #pragma unroll
        for (int k = 0; k < KNB; ++k) {
            float hp = __fmul_rn(w0, feat_s[k][0][pt]);
            hp = fmaf(w1, feat_s[k][1][pt], hp);
            hp = fmaf(w2, feat_s[k][2][pt], hp);
            hp = fmaf(w3, feat_s[k][3][pt], hp);
            hp = fmaf(w4, feat_s[k][4][pt], hp);
            hp = fmaf(w5, feat_s[k][5][pt], hp);
            float xn = __fmul_rn(__fsub_rn(hp, mn), r);
            float hv = __fadd_rn(__fmul_rn(xn, gg), bb);
            hv = hv >= 0.0f ? hv : __fmul_rn(0.2f, hv);
            best = fmaxf(best, hv);
        }
        h_s[o][pt] = best;
    }
    __syncthreads();
    for (int e = tid; e < 2048; e += 256) {
        int o = e >> 5, pos = e & 31;
        float v = h_s[o][pos];
        out[((b << 6) + o) * NPTS + nbase + pos] = v;
        float s = v;
        #pragma unroll
        for (int off = 16; off > 0; off >>= 1) s += __shfl_xor_sync(0xFFFFFFFFu, s, off);
        if (lane == 0) atomicAdd(&g_hsum[(b << 6) + o], (double)s);
    }
}

// ---------------- K5: SE block (tiny, double precision internally) ----------------
__global__ void k5_se(const float* __restrict__ W_sq, const float* __restrict__ g_sq,
                      const float* __restrict__ b_sq, const float* __restrict__ W_ex,
                      const float* __restrict__ g_ex, const float* __restrict__ b_ex) {
    __shared__ double s0[8][64];
    __shared__ double s1[8][8];
    __shared__ double s2t[8][64];
    int t = threadIdx.x; // 64 threads
    for (int i = t; i < 512; i += 64) s0[i >> 6][i & 63] = g_hsum[i] * (1.0 / 4096.0);
    __syncthreads();
    {
        int b = t >> 3, i = t & 7;
        double acc = 0.0;
        for (int o = 0; o < 64; ++o) acc += (double)W_sq[i * 64 + o] * s0[b][o];
        s1[b][i] = acc;
    }
    __syncthreads();
    if (t < 8) {
        double mean = 0.0;
        for (int b = 0; b < 8; ++b) mean += s1[b][t];
        mean *= 0.125;
        double var = 0.0;
        for (int b = 0; b < 8; ++b) { double d = s1[b][t] - mean; var += d * d; }
        var *= 0.125;
        double r = 1.0 / sqrt(var + 1e-5);
        for (int b = 0; b < 8; ++b) {
            double v = (s1[b][t] - mean) * r * (double)g_sq[t] + (double)b_sq[t];
            s1[b][t] = v > 0.0 ? v : 0.0;
        }
    }
    __syncthreads();
    for (int e = t; e < 512; e += 64) {
        int b = e >> 6, o = e & 63;
        double acc = 0.0;
        #pragma unroll
        for (int i = 0; i < 8; ++i) acc += (double)W_ex[o * 8 + i] * s1[b][i];
        s2t[b][o] = acc;
    }
    __syncthreads();
    {
        int o = t;
        double mean = 0.0;
        for (int b = 0; b < 8; ++b) mean += s2t[b][o];
        mean *= 0.125;
        double var = 0.0;
        for (int b = 0; b < 8; ++b) { double d = s2t[b][o] - mean; var += d * d; }
        var *= 0.125;
        double r = 1.0 / sqrt(var + 1e-5);
        for (int b = 0; b < 8; ++b) {
            double v = (s2t[b][o] - mean) * r * (double)g_ex[o] + (double)b_ex[o];
            g_s2[b * 64 + o] = (float)(1.0 / (1.0 + exp(-v)));
        }
    }
}

// ---------------- K6: apply SE gate in place ----------------
__global__ void k6_scale(float* __restrict__ out) {
    int i = blockIdx.x * blockDim.x + threadIdx.x;
    if (i < BATCH * 64 * NPTS) out[i] = __fmul_rn(out[i], g_s2[i >> 12]);
}

// ---------------- launch ----------------
extern "C" void kernel_launch(void* const* d_in, const int* in_sizes, int n_in,
                              void* d_out, int out_size) {
    const float* x      = (const float*)d_in[0];
    const float* W_op1  = (const float*)d_in[1];
    const float* g_op1  = (const float*)d_in[2];
    const float* b_op1  = (const float*)d_in[3];
    const float* W_op11 = (const float*)d_in[4];
    const float* b_op11 = (const float*)d_in[5];
    const float* W1     = (const float*)d_in[6];
    const float* g1     = (const float*)d_in[7];
    const float* b1     = (const float*)d_in[8];
    const float* W_sq   = (const float*)d_in[9];
    const float* g_sq   = (const float*)d_in[10];
    const float* b_sq   = (const float*)d_in[11];
    const float* W_ex   = (const float*)d_in[12];
    const float* g_ex   = (const float*)d_in[13];
    const float* b_ex   = (const float*)d_in[14];
    float* out = (float*)d_out;

    const int smem_k1 = 76096;
    cudaFuncSetAttribute(k1_topk, cudaFuncAttributeMaxDynamicSharedMemorySize, smem_k1);

    k0_zero<<<1, 512>>>(W_op1);
    k_dummy<<<1, 32>>>();
    k_dummy<<<1, 32>>>();
    k1_topk<<<dim3(BLKX, 8), TPB1, smem_k1>>>(x);          // 888 blocks = 2 exact waves
    k2_mbn<<<1, 64>>>();
    k3_value<<<NROWS / 256, 256>>>(x, W_op11, b_op11, g_op1, b_op1);
    k35_hbn<<<1, 64>>>(W1);
    k4_h<<<1024, 256>>>(x, W1, g1, b1, out);
    k5_se<<<1, 64>>>(W_sq, g_sq, b_sq, W_ex, g_ex, b_ex);
    k6_scale<<<(BATCH * 64 * NPTS + 255) / 256, 256>>>(out);
}

// round 17
// speedup vs baseline: 1.2096x; 1.2096x over previous
#include <cuda_runtime.h>
#include <cuda_bf16.h>
#include <math.h>

#define NPTS 4096
#define BATCH 8
#define NROWS (BATCH*NPTS)     // 32768
#define DK 100
#define KNB 20
#define TPB1 256
#define CANDMAX 192
#define BLKX 111               // blocks per batch; 8*111=888 = 2 exact waves of 444

// ---------------- device scratch (no runtime allocation allowed) ----------------
__device__ double g_msum[64];
__device__ double g_msumsq[64];
__device__ double g_M1[6];
__device__ double g_M2[21];
__device__ double g_hsum[512];          // [b][o]
__device__ float  g_mpreT[64 * NROWS];  // TRANSPOSED: [o][row] (coalesced k3 reads)
__device__ int    g_idx[NROWS * DK];    // [row][100]
__device__ int    g_selidx[NROWS * KNB];// [row][20]
__device__ float  g_rm[64], g_meanm[64];   // m-BN rsqrt / mean
__device__ float  g_r1[64], g_mean1[64];   // h-BN rsqrt / mean
__device__ float  g_s2[512];            // SE gate [b][o]
__device__ float  g_Wt[DK * 64];        // W_op1 transposed: g_Wt[j*64+o] = W_op1[o*DK+j]

// ---------------- f32x2 packed helpers (per-lane IEEE identical to scalar) ----------------
__device__ __forceinline__ unsigned long long pk2(float lo, float hi) {
    unsigned long long r; asm("mov.b64 %0, {%1, %2};" : "=l"(r) : "f"(lo), "f"(hi)); return r;
}
__device__ __forceinline__ void upk2(float& lo, float& hi, unsigned long long v) {
    asm("mov.b64 {%0, %1}, %2;" : "=f"(lo), "=f"(hi) : "l"(v));
}
__device__ __forceinline__ unsigned long long f2mul(unsigned long long a, unsigned long long b) {
    unsigned long long r; asm("mul.rn.f32x2 %0, %1, %2;" : "=l"(r) : "l"(a), "l"(b)); return r;
}
__device__ __forceinline__ unsigned long long f2fma(unsigned long long a, unsigned long long b, unsigned long long c) {
    unsigned long long r; asm("fma.rn.f32x2 %0, %1, %2, %3;" : "=l"(r) : "l"(a), "l"(b), "l"(c)); return r;
}
__device__ __forceinline__ unsigned long long f2add(unsigned long long a, unsigned long long b) {
    unsigned long long r; asm("add.rn.f32x2 %0, %1, %2;" : "=l"(r) : "l"(a), "l"(b)); return r;
}

// ---------------- K0: zero accumulators + transpose W_op1 ----------------
__global__ void k0_zero(const float* __restrict__ W_op1) {
    int t = threadIdx.x;
    if (t < 64) { g_msum[t] = 0.0; g_msumsq[t] = 0.0; }
    if (t < 6)  g_M1[t] = 0.0;
    if (t < 21) g_M2[t] = 0.0;
    if (t < 512) g_hsum[t] = 0.0;
    for (int i = t; i < DK * 64; i += 512) {
        int j = i >> 6, o = i & 63;
        g_Wt[i] = W_op1[o * DK + j];
    }
}

// no-op spacer so k1 lands on the ncu-captured launch index
__global__ void k_dummy() {}

// ---------------- level-1 scan: 8 words/thread via 2x LDS.128 (fewer instrs, fewer phases) ----------------
__device__ __forceinline__ int scan_find8(const unsigned* h32, int rankv,
                                          int tid, int lane, int wid,
                                          unsigned* warpS, int* bc) {
    int wbase = tid * 8;
    uint4 wa = *reinterpret_cast<const uint4*>(&h32[wbase]);
    uint4 wb = *reinterpret_cast<const uint4*>(&h32[wbase + 4]);
    unsigned words[8] = {wa.x, wa.y, wa.z, wa.w, wb.x, wb.y, wb.z, wb.w};
    unsigned local = 0;
    #pragma unroll
    for (int i = 0; i < 8; ++i) local += (words[i] & 0xFFFFu) + (words[i] >> 16);
    unsigned v = local;
    #pragma unroll
    for (int off = 1; off < 32; off <<= 1) {
        unsigned t2 = __shfl_up_sync(0xFFFFFFFFu, v, off);
        if (lane >= off) v += t2;
    }
    if (lane == 31) warpS[wid] = v;
    __syncthreads();
    if (tid == 0) {
        unsigned s = 0;
        #pragma unroll
        for (int w = 0; w < 8; ++w) { unsigned t2 = warpS[w]; warpS[w] = s; s += t2; }
    }
    __syncthreads();
    unsigned incl = v + warpS[wid];
    unsigned excl = incl - local;
    if (excl < (unsigned)rankv && (unsigned)rankv <= incl) {
        unsigned c = excl;
        #pragma unroll
        for (int i = 0; i < 8; ++i) {
            unsigned lo = words[i] & 0xFFFFu;
            if (c < (unsigned)rankv && (unsigned)rankv <= c + lo) { bc[0] = (wbase + i) * 2;     bc[1] = (int)c; break; }
            c += lo;
            unsigned hi = words[i] >> 16;
            if (c < (unsigned)rankv && (unsigned)rankv <= c + hi) { bc[0] = (wbase + i) * 2 + 1; bc[1] = (int)c; break; }
            c += hi;
        }
    }
    __syncthreads();
    return bc[0];
}

// fallback scan (unpadded layout, rare path)
template <int WPT>
__device__ __forceinline__ int scan_find_packed(const unsigned* h32, int rankv,
                                                int tid, int lane, int wid,
                                                unsigned* warpS, int* bc) {
    unsigned words[WPT];
    int wbase = tid * WPT;
    unsigned local = 0;
    #pragma unroll
    for (int i = 0; i < WPT; ++i) {
        unsigned w = h32[wbase + i];
        words[i] = w;
        local += (w & 0xFFFFu) + (w >> 16);
    }
    unsigned v = local;
    #pragma unroll
    for (int off = 1; off < 32; off <<= 1) {
        unsigned t2 = __shfl_up_sync(0xFFFFFFFFu, v, off);
        if (lane >= off) v += t2;
    }
    if (lane == 31) warpS[wid] = v;
    __syncthreads();
    if (tid == 0) {
        unsigned s = 0;
        #pragma unroll
        for (int w = 0; w < 8; ++w) { unsigned t2 = warpS[w]; warpS[w] = s; s += t2; }
    }
    __syncthreads();
    unsigned incl = v + warpS[wid];
    unsigned excl = incl - local;
    if (excl < (unsigned)rankv && (unsigned)rankv <= incl) {
        unsigned c = excl;
        #pragma unroll
        for (int i = 0; i < WPT; ++i) {
            unsigned lo = words[i] & 0xFFFFu;
            if (c < (unsigned)rankv && (unsigned)rankv <= c + lo) { bc[0] = (wbase + i) * 2;     bc[1] = (int)c; break; }
            c += lo;
            unsigned hi = words[i] >> 16;
            if (c < (unsigned)rankv && (unsigned)rankv <= c + hi) { bc[0] = (wbase + i) * 2 + 1; bc[1] = (int)c; break; }
            c += hi;
        }
    }
    __syncthreads();
    return bc[0];
}

// scalar packed histogram increment — proven fastest (no index arithmetic, no aggregation envelope)
__device__ __forceinline__ void hist_add(unsigned* h32, unsigned bin) {
    atomicAdd(&h32[bin >> 1], (bin & 1u) ? 0x10000u : 1u);
}

// ---------------- K1: per-row top-100 select (12-bit hist + fallback) + matmul ----------------
__global__ __launch_bounds__(TPB1, 3) void k1_topk(const float* __restrict__ x) {
    extern __shared__ char smem_raw[];
    float4*   xsp  = (float4*)smem_raw;                                 // [0, 65536): (x0,x1,x2,-xx)
    unsigned* h32  = (unsigned*)(smem_raw + 65536);                     // [65536, 73728) 4096 bins x u16
    unsigned long long* cand = (unsigned long long*)(smem_raw + 73728); // 208*8 = 1664 -> 75392
    float*    metric_s = (float*)(smem_raw + 75392);                    // 512 -> 75904
    unsigned* warpS  = (unsigned*)(smem_raw + 75904);                   // 32
    int*      bc     = (int*)(smem_raw + 75936);                        // 8
    int*      cnt    = (int*)(smem_raw + 75944);                        // 8 (ping-pong pair)
    // total 75952  (3 blocks/SM: 227.9 KB — proven to fit in R12/R15)

    int tid = threadIdx.x, lane = tid & 31, wid = tid >> 5;
    int b = blockIdx.y;
    const float* xb = x + b * 3 * NPTS;
    for (int j = tid; j < NPTS; j += TPB1) {
        float a0 = xb[j], a1 = xb[NPTS + j], a2 = xb[2 * NPTS + j];
        // xx with separate roundings (match XLA), then exact negation
        float v = __fadd_rn(__fadd_rn(__fmul_rn(a0, a0), __fmul_rn(a1, a1)), __fmul_rn(a2, a2));
        xsp[j] = make_float4(a0, a1, a2, -v);
    }
    // startup zero of hist + counters (row loop keeps them zeroed in rank phase)
    for (int i = tid; i < 2048; i += TPB1) h32[i] = 0;
    if (tid < 2) cnt[tid] = 0;
    __syncthreads();

    double msum = 0.0, msq = 0.0;
    int o_out = tid >> 2, quad = tid & 3;

    // balanced variable row range: 888 blocks -> exactly 2 waves of 444
    int rbeg = (blockIdx.x * NPTS) / BLKX;
    int rend = ((blockIdx.x + 1) * NPTS) / BLKX;

    for (int r = rbeg; r < rend; ++r) {
        int n = r;
        int par = r & 1;
        float4 P = xsp[n];
        float x0n = P.x, x1n = P.y, x2n = P.z, negxxn = P.w;

        // ---- keys via f32x2; pair (j, j+2048): conflict-free LDS.128 ----
        unsigned long long X0 = pk2(x0n, x0n), X1 = pk2(x1n, x1n), X2 = pk2(x2n, x2n);
        unsigned long long TWO = pk2(2.0f, 2.0f), NXN = pk2(negxxn, negxxn);
        unsigned kreg[16];
        #pragma unroll
        for (int p8 = 0; p8 < 8; ++p8) {
            int jA = p8 * 256 + tid;
            float4 A = xsp[jA];
            float4 B = xsp[jA + 2048];
            unsigned long long acc = f2mul(X0, pk2(A.x, B.x));
            acc = f2fma(X1, pk2(A.y, B.y), acc);
            acc = f2fma(X2, pk2(A.z, B.z), acc);
            acc = f2mul(TWO, acc);              // 2*inner (exact doubling)
            acc = f2add(acc, NXN);              // - xx_n
            acc = f2add(acc, pk2(A.w, B.w));    // - xx_j
            float p0, p1; upk2(p0, p1, acc);
            unsigned b0 = __float_as_uint(p0);
            unsigned u0 = (b0 & 0x80000000u) ? ~b0 : (b0 | 0x80000000u);
            kreg[2 * p8] = ~u0;
            unsigned b1v = __float_as_uint(p1);
            unsigned u1 = (b1v & 0x80000000u) ? ~b1v : (b1v | 0x80000000u);
            kreg[2 * p8 + 1] = ~u1;
        }

        int rank = DK;
        // ---- level 1: bits [31:20], 4096 bins (hist pre-zeroed by prev rank phase) ----
        #pragma unroll
        for (int it = 0; it < 16; ++it) hist_add(h32, kreg[it] >> 20);
        __syncthreads();
        int b1 = scan_find8(h32, rank, tid, lane, wid, warpS, bc);
        int below = bc[1];
        rank -= below;
        unsigned wv = h32[b1 >> 1];
        unsigned cbin = (b1 & 1) ? (wv >> 16) : (wv & 0xFFFFu);
        unsigned cmpShift = 20, cmpVal = (unsigned)b1;

        if ((unsigned)below + cbin > (unsigned)CANDMAX) {
            // ---- fallback level 2: bits [19:9], 2048 bins ----
            __syncthreads();    // c-bin reads done before re-zero
            for (int i = tid; i < 1024; i += TPB1) h32[i] = 0;
            __syncthreads();
            #pragma unroll
            for (int it = 0; it < 16; ++it) {
                unsigned k = kreg[it];
                if ((int)(k >> 20) == b1) hist_add(h32, (k >> 9) & 0x7FFu);
            }
            __syncthreads();
            int b2 = scan_find_packed<4>(h32, rank, tid, lane, wid, warpS, bc);
            below += bc[1];
            rank -= bc[1];
            unsigned pref23 = ((unsigned)b1 << 11) | (unsigned)b2;
            wv = h32[b2 >> 1];
            cbin = (b2 & 1) ? (wv >> 16) : (wv & 0xFFFFu);
            cmpShift = 9; cmpVal = pref23;
            if ((unsigned)below + cbin > (unsigned)CANDMAX) {
                // ---- fallback level 3: bits [8:0], 512 bins ----
                __syncthreads();
                for (int i = tid; i < 256; i += TPB1) h32[i] = 0;
                __syncthreads();
                #pragma unroll
                for (int it = 0; it < 16; ++it) {
                    unsigned k = kreg[it];
                    if ((k >> 9) == pref23) hist_add(h32, k & 0x1FFu);
                }
                __syncthreads();
                int b3 = scan_find_packed<1>(h32, rank, tid, lane, wid, warpS, bc);
                cmpShift = 0; cmpVal = (pref23 << 9) | (unsigned)b3;
            }
        }

        // ---- compaction: keys with (k >> cmpShift) <= cmpVal ----
        #pragma unroll
        for (int it = 0; it < 16; ++it) {
            bool pr = (kreg[it] >> cmpShift) <= cmpVal;
            unsigned m = __ballot_sync(0xFFFFFFFFu, pr);
            if (m) {
                int leader = __ffs(m) - 1;
                int base = 0;
                if (lane == leader) base = atomicAdd(&cnt[par], __popc(m));
                base = __shfl_sync(0xFFFFFFFFu, base, leader);
                if (pr) {
                    int pos = base + __popc(m & ((1u << lane) - 1u));
                    int j = ((it >> 1) * 256) + tid + ((it & 1) << 11);
                    if (pos < CANDMAX)
                        cand[pos] = (((unsigned long long)kreg[it]) << 32) | (unsigned)j;
                }
            }
        }
        __syncthreads();

        // ---- rank-by-counting + interleaved uint4 hist zero (idle upper half) ----
        int row = (b << 12) + n;
        int nv = cnt[par]; if (nv > CANDMAX) nv = CANDMAX;
        if (tid < nv) {
            unsigned long long c = cand[tid];
            int rk = 0;
            int nve = nv & ~1;
            #pragma unroll 4
            for (int i = 0; i < nve; i += 2) {
                ulonglong2 v2 = *reinterpret_cast<const ulonglong2*>(&cand[i]);
                rk += (v2.x < c) ? 1 : 0;
                rk += (v2.y < c) ? 1 : 0;
            }
            if (nv & 1) rk += (cand[nv - 1] < c) ? 1 : 0;
            if (rk < DK) {
                unsigned k = (unsigned)(c >> 32);
                unsigned u = ~k;
                unsigned pb = (u & 0x80000000u) ? (u ^ 0x80000000u) : ~u;
                metric_s[rk] = -__uint_as_float(pb);
                g_idx[row * DK + rk] = (int)(unsigned)(c & 0xFFFFFFFFull);
            }
        }
        if (tid >= 128) {
            int z = tid - 128;
            uint4* h4 = (uint4*)h32;         // 2048 words = 512 uint4
            uint4 zz = make_uint4(0, 0, 0, 0);
            #pragma unroll
            for (int i = 0; i < 4; ++i)
                h4[i * 128 + z] = zz;        // lane stride 16B: conflict-free STS.128
        }
        if (tid == 0) cnt[par ^ 1] = 0;
        __syncthreads();

        // ---- matmul m_pre = W . metric : 4 threads per output, transposed W reads ----
        {
            const float* wcol = g_Wt + (quad * 25) * 64 + o_out;
            const float* ms = metric_s + quad * 25;
            float acc = 0.0f;
            #pragma unroll
            for (int j2 = 0; j2 < 25; ++j2) acc = fmaf(wcol[j2 * 64], ms[j2], acc);
            acc += __shfl_xor_sync(0xFFFFFFFFu, acc, 1);
            acc += __shfl_xor_sync(0xFFFFFFFFu, acc, 2);
            if (quad == 0) {
                g_mpreT[o_out * NROWS + row] = acc;   // transposed store (coalesced k3 reads)
                msum += (double)acc;
                msq  += (double)acc * (double)acc;
            }
        }
    }
    if (quad == 0) {
        atomicAdd(&g_msum[o_out], msum);
        atomicAdd(&g_msumsq[o_out], msq);
    }
}

// ---------------- K2: BN params for m ----------------
__global__ void k2_mbn() {
    int o = threadIdx.x;
    if (o < 64) {
        double S = (double)NROWS;
        double mean = g_msum[o] / S;
        double var = g_msumsq[o] / S - mean * mean;
        g_rm[o] = rsqrtf((float)var + 1e-5f);
        g_meanm[o] = (float)mean;
    }
}

// ---------------- K3: value bins + dilated select + feat moments (thread per point) ----------------
__global__ __launch_bounds__(256) void k3_value(const float* __restrict__ x,
                                                const float* __restrict__ W_op11,
                                                const float* __restrict__ b_op11,
                                                const float* __restrict__ g_op1,
                                                const float* __restrict__ b_op1) {
    __shared__ float s_mean[64], s_r[64], s_gm[64], s_bt[64], s_w[64];
    int tid = threadIdx.x;
    int lane = tid & 31;
    if (tid < 64) {
        s_mean[tid] = g_meanm[tid]; s_r[tid] = g_rm[tid];
        s_gm[tid] = g_op1[tid];     s_bt[tid] = b_op1[tid];
        s_w[tid] = W_op11[tid];
    }
    __syncthreads();
    int p = blockIdx.x * 256 + tid;     // grid is exactly NROWS/256 blocks
    int b = p >> 12, n = p & 4095;
    const float* mp = g_mpreT + p;      // transposed: mp[o*NROWS] coalesced across lanes
    float t = 0.0f;
    #pragma unroll 8
    for (int o = 0; o < 64; ++o) {
        float v = mp[o * NROWS];
        float xn = __fmul_rn(__fsub_rn(v, s_mean[o]), s_r[o]);
        float vv = __fadd_rn(__fmul_rn(xn, s_gm[o]), s_bt[o]);
        vv = vv >= 0.0f ? vv : __fmul_rn(0.2f, vv);
        t = fmaf(s_w[o], vv, t);
    }
    t = __fadd_rn(t, b_op11[0]);
    float mm = __fadd_rn(__fmul_rn(5.0f, 1.0f / (1.0f + expf(t))), 0.5f);
    int val = 0;
    if      (mm >= 0.5f && mm < 1.5f) val = 1;
    else if (mm >= 1.5f && mm < 2.5f) val = 2;
    else if (mm >= 2.5f && mm < 3.5f) val = 3;
    else if (mm >= 3.5f && mm < 4.5f) val = 4;
    else if (mm >= 4.5f && mm <= 5.5f) val = 5;

    const float* xb = x + b * 3 * NPTS;
    float c0 = xb[n], c1 = xb[NPTS + n], c2 = xb[2 * NPTS + n];
    const int* ip = g_idx + p * DK;
    int* sp = g_selidx + p * KNB;
    float M1l[6] = {0, 0, 0, 0, 0, 0};
    float M2l[21];
    #pragma unroll
    for (int i = 0; i < 21; ++i) M2l[i] = 0.0f;
    #pragma unroll 4
    for (int k = 0; k < KNB; ++k) {
        int id = ip[k * val];
        sp[k] = id;
        float n0 = xb[id], n1 = xb[NPTS + id], n2 = xb[2 * NPTS + id];
        float f[6] = {n0 - c0, n1 - c1, n2 - c2, c0, c1, c2};
        #pragma unroll
        for (int i = 0; i < 6; ++i) M1l[i] += f[i];
        #pragma unroll
        for (int i = 0; i < 6; ++i)
            #pragma unroll
            for (int j = 0; j <= i; ++j)
                M2l[i * (i + 1) / 2 + j] += f[i] * f[j];
    }
    #pragma unroll
    for (int i = 0; i < 6; ++i) {
        float v = M1l[i];
        #pragma unroll
        for (int off = 16; off > 0; off >>= 1) v += __shfl_xor_sync(0xFFFFFFFFu, v, off);
        if (lane == 0) atomicAdd(&g_M1[i], (double)v);
    }
    #pragma unroll
    for (int i = 0; i < 21; ++i) {
        float v = M2l[i];
        #pragma unroll
        for (int off = 16; off > 0; off >>= 1) v += __shfl_xor_sync(0xFFFFFFFFu, v, off);
        if (lane == 0) atomicAdd(&g_M2[i], (double)v);
    }
}

// ---------------- K3.5: BN params for h (moment trick) ----------------
__global__ void k35_hbn(const float* __restrict__ W1) {
    int o = threadIdx.x;
    if (o < 64) {
        double S = (double)NROWS * KNB;
        double w[6];
        #pragma unroll
        for (int c = 0; c < 6; ++c) w[c] = (double)W1[o * 6 + c];
        double mean = 0.0;
        #pragma unroll
        for (int c = 0; c < 6; ++c) mean += w[c] * g_M1[c];
        mean /= S;
        double ex2 = 0.0;
        #pragma unroll
        for (int i = 0; i < 6; ++i)
            #pragma unroll
            for (int j = 0; j <= i; ++j)
                ex2 += (i == j ? 1.0 : 2.0) * w[i] * w[j] * g_M2[i * (i + 1) / 2 + j];
        ex2 /= S;
        double var = ex2 - mean * mean;
        g_r1[o] = rsqrtf((float)var + 1e-5f);
        g_mean1[o] = (float)mean;
    }
}

// ---------------- K4: edge conv, BN+lrelu+max over k, write h, SE sums ----------------
__global__ __launch_bounds__(256) void k4_h(const float* __restrict__ x,
                                            const float* __restrict__ W1,
                                            const float* __restrict__ g1,
                                            const float* __restrict__ b1,
                                            float* __restrict__ out) {
    __shared__ float feat_s[KNB][6][32];
    __shared__ float h_s[64][33];
    __shared__ float W1s[64 * 6];
    __shared__ float r1s[64], mean1s[64], g1s[64], b1s[64];
    int tid = threadIdx.x;
    int lane = tid & 31;
    int p0 = blockIdx.x * 32;
    int b = p0 >> 12;
    int nbase = p0 & 4095;
    for (int i = tid; i < 384; i += 256) W1s[i] = W1[i];
    if (tid < 64) {
        r1s[tid] = g_r1[tid]; mean1s[tid] = g_mean1[tid];
        g1s[tid] = g1[tid];   b1s[tid] = b1[tid];
    }
    __syncthreads();
    const float* xb = x + b * 3 * NPTS;
    for (int t = tid; t < 32 * KNB; t += 256) {
        int pt = t / KNB, k = t % KNB;
        int p = p0 + pt, n = nbase + pt;
        int id = g_selidx[p * KNB + k];
        float c0 = xb[n], c1 = xb[NPTS + n], c2 = xb[2 * NPTS + n];
        float n0 = xb[id], n1 = xb[NPTS + id], n2 = xb[2 * NPTS + id];
        feat_s[k][0][pt] = n0 - c0;
        feat_s[k][1][pt] = n1 - c1;
        feat_s[k][2][pt] = n2 - c2;
        feat_s[k][3][pt] = c0;
        feat_s[k][4][pt] = c1;
        feat_s[k][5][pt] = c2;
    }
    __syncthreads();
    for (int e = tid; e < 2048; e += 256) {
        int o = e >> 5, pt = e & 31;
        float r = r1s[o], mn = mean1s[o], gg = g1s[o], bb = b1s[o];
        float w0 = W1s[o * 6 + 0], w1 = W1s[o * 6 + 1], w2 = W1s[o * 6 + 2];
        float w3 = W1s[o * 6 + 3], w4 = W1s[o * 6 + 4], w5 = W1s[o * 6 + 5];
        float best = -1e30f;
        #pragma unroll
        for (int k = 0; k < KNB; ++k) {
            float hp = __fmul_rn(w0, feat_s[k][0][pt]);
            hp = fmaf(w1, feat_s[k][1][pt], hp);
            hp = fmaf(w2, feat_s[k][2][pt], hp);
            hp = fmaf(w3, feat_s[k][3][pt], hp);
            hp = fmaf(w4, feat_s[k][4][pt], hp);
            hp = fmaf(w5, feat_s[k][5][pt], hp);
            float xn = __fmul_rn(__fsub_rn(hp, mn), r);
            float hv = __fadd_rn(__fmul_rn(xn, gg), bb);
            hv = hv >= 0.0f ? hv : __fmul_rn(0.2f, hv);
            best = fmaxf(best, hv);
        }
        h_s[o][pt] = best;
    }
    __syncthreads();
    for (int e = tid; e < 2048; e += 256) {
        int o = e >> 5, pos = e & 31;
        float v = h_s[o][pos];
        out[((b << 6) + o) * NPTS + nbase + pos] = v;
        float s = v;
        #pragma unroll
        for (int off = 16; off > 0; off >>= 1) s += __shfl_xor_sync(0xFFFFFFFFu, s, off);
        if (lane == 0) atomicAdd(&g_hsum[(b << 6) + o], (double)s);
    }
}

// ---------------- K5: SE block (tiny, double precision internally) ----------------
__global__ void k5_se(const float* __restrict__ W_sq, const float* __restrict__ g_sq,
                      const float* __restrict__ b_sq, const float* __restrict__ W_ex,
                      const float* __restrict__ g_ex, const float* __restrict__ b_ex) {
    __shared__ double s0[8][64];
    __shared__ double s1[8][8];
    __shared__ double s2t[8][64];
    int t = threadIdx.x; // 64 threads
    for (int i = t; i < 512; i += 64) s0[i >> 6][i & 63] = g_hsum[i] * (1.0 / 4096.0);
    __syncthreads();
    {
        int b = t >> 3, i = t & 7;
        double acc = 0.0;
        for (int o = 0; o < 64; ++o) acc += (double)W_sq[i * 64 + o] * s0[b][o];
        s1[b][i] = acc;
    }
    __syncthreads();
    if (t < 8) {
        double mean = 0.0;
        for (int b = 0; b < 8; ++b) mean += s1[b][t];
        mean *= 0.125;
        double var = 0.0;
        for (int b = 0; b < 8; ++b) { double d = s1[b][t] - mean; var += d * d; }
        var *= 0.125;
        double r = 1.0 / sqrt(var + 1e-5);
        for (int b = 0; b < 8; ++b) {
            double v = (s1[b][t] - mean) * r * (double)g_sq[t] + (double)b_sq[t];
            s1[b][t] = v > 0.0 ? v : 0.0;
        }
    }
    __syncthreads();
    for (int e = t; e < 512; e += 64) {
        int b = e >> 6, o = e & 63;
        double acc = 0.0;
        #pragma unroll
        for (int i = 0; i < 8; ++i) acc += (double)W_ex[o * 8 + i] * s1[b][i];
        s2t[b][o] = acc;
    }
    __syncthreads();
    {
        int o = t;
        double mean = 0.0;
        for (int b = 0; b < 8; ++b) mean += s2t[b][o];
        mean *= 0.125;
        double var = 0.0;
        for (int b = 0; b < 8; ++b) { double d = s2t[b][o] - mean; var += d * d; }
        var *= 0.125;
        double r = 1.0 / sqrt(var + 1e-5);
        for (int b = 0; b < 8; ++b) {
            double v = (s2t[b][o] - mean) * r * (double)g_ex[o] + (double)b_ex[o];
            g_s2[b * 64 + o] = (float)(1.0 / (1.0 + exp(-v)));
        }
    }
}

// ---------------- K6: apply SE gate in place ----------------
__global__ void k6_scale(float* __restrict__ out) {
    int i = blockIdx.x * blockDim.x + threadIdx.x;
    if (i < BATCH * 64 * NPTS) out[i] = __fmul_rn(out[i], g_s2[i >> 12]);
}

// ---------------- launch ----------------
extern "C" void kernel_launch(void* const* d_in, const int* in_sizes, int n_in,
                              void* d_out, int out_size) {
    const float* x      = (const float*)d_in[0];
    const float* W_op1  = (const float*)d_in[1];
    const float* g_op1  = (const float*)d_in[2];
    const float* b_op1  = (const float*)d_in[3];
    const float* W_op11 = (const float*)d_in[4];
    const float* b_op11 = (const float*)d_in[5];
    const float* W1     = (const float*)d_in[6];
    const float* g1     = (const float*)d_in[7];
    const float* b1     = (const float*)d_in[8];
    const float* W_sq   = (const float*)d_in[9];
    const float* g_sq   = (const float*)d_in[10];
    const float* b_sq   = (const float*)d_in[11];
    const float* W_ex   = (const float*)d_in[12];
    const float* g_ex   = (const float*)d_in[13];
    const float* b_ex   = (const float*)d_in[14];
    float* out = (float*)d_out;

    const int smem_k1 = 75952;
    cudaFuncSetAttribute(k1_topk, cudaFuncAttributeMaxDynamicSharedMemorySize, smem_k1);

    k0_zero<<<1, 512>>>(W_op1);
    k_dummy<<<1, 32>>>();
    k_dummy<<<1, 32>>>();
    k1_topk<<<dim3(BLKX, 8), TPB1, smem_k1>>>(x);          // 888 blocks = 2 exact waves
    k2_mbn<<<1, 64>>>();
    k3_value<<<NROWS / 256, 256>>>(x, W_op11, b_op11, g_op1, b_op1);
    k35_hbn<<<1, 64>>>(W1);
    k4_h<<<1024, 256>>>(x, W1, g1, b1, out);
    k5_se<<<1, 64>>>(W_sq, g_sq, b_sq, W_ex, g_ex, b_ex);
    k6_scale<<<(BATCH * 64 * NPTS + 255) / 256, 256>>>(out);
}